// round 6
// baseline (speedup 1.0000x reference)
#include <cuda_runtime.h>
#include <cuda_bf16.h>
#include <stdint.h>
#include <math.h>

// ---------------------------------------------------------------------------
// Mixtral sparse MoE block, GB300 (sm_103a)
// B=2, S=1024 -> T=2048 tokens, H=1024, E=8, F=2816, TOP_K=2
// Outputs (concatenated fp32): final_hidden_states [2,1024,1024], router_logits [2048,8]
// ---------------------------------------------------------------------------

constexpr int T = 2048;
constexpr int H = 1024;
constexpr int E = 8;
constexpr int F = 2816;
constexpr int AMAX = 2 * T;          // total assignments (top-2)
constexpr int APAD = AMAX + 128;     // pad so last tile can over-read safely

// Scratch (static __device__ globals: allocation-free rule)
__device__ float g_act[(size_t)APAD * F];   // post-SwiGLU activations per slot
__device__ float g_y[(size_t)APAD * H];     // per-slot down-proj results
__device__ int   g_cnt[E];
__device__ int   g_off[E];
__device__ int   g_cur[E];
__device__ int   g_top_e[T * 2];
__device__ float g_top_w[T * 2];
__device__ int   g_assign_tok[AMAX];
__device__ float g_assign_w[AMAX];
__device__ int   g_tok2slot[T * 2];
__device__ float g_logits_dummy[T * E];     // fallback if out buffer lacks logits region

// ---------------------------------------------------------------------------
// tf32 helpers (legacy mma.sync path; tcgen05 port planned after profiling)
// ---------------------------------------------------------------------------
__device__ __forceinline__ uint32_t f2tf32(float f) {
    uint32_t u;
    asm("cvt.rna.tf32.f32 %0, %1;" : "=r"(u) : "f"(f));
    return u;
}

__device__ __forceinline__ void mma_tf32(float* c, const uint32_t* a, const uint32_t* b) {
    asm volatile(
        "mma.sync.aligned.m16n8k8.row.col.f32.tf32.tf32.f32 "
        "{%0,%1,%2,%3}, {%4,%5,%6,%7}, {%8,%9}, {%0,%1,%2,%3};\n"
        : "+f"(c[0]), "+f"(c[1]), "+f"(c[2]), "+f"(c[3])
        : "r"(a[0]), "r"(a[1]), "r"(a[2]), "r"(a[3]), "r"(b[0]), "r"(b[1]));
}

// ---------------------------------------------------------------------------
// 0) zero per-launch state (graph replays reuse the globals)
// ---------------------------------------------------------------------------
__global__ void zero_counts_kernel() {
    if (threadIdx.x < E) g_cnt[threadIdx.x] = 0;
}

// ---------------------------------------------------------------------------
// 1) Router: logits (fp32 exact), top-2, pairwise-softmax weights.
//    warp-per-token; gate_w (32KB) staged in smem.
// ---------------------------------------------------------------------------
__global__ __launch_bounds__(256) void router_kernel(
    const float* __restrict__ x, const float* __restrict__ gw,
    float* __restrict__ logits_out) {
    __shared__ float sgw[E * H];
    int tid = threadIdx.x;
    for (int i = tid; i < E * H; i += 256) sgw[i] = gw[i];
    __syncthreads();

    int warp = tid >> 5, lane = tid & 31;
    int t = blockIdx.x * 8 + warp;

    float xr[32];
    const float* xp = x + (size_t)t * H;
#pragma unroll
    for (int i = 0; i < 32; i++) xr[i] = xp[i * 32 + lane];

    float l[E];
#pragma unroll
    for (int e = 0; e < E; e++) {
        float acc = 0.f;
        const float* g = sgw + e * H;
#pragma unroll
        for (int i = 0; i < 32; i++) acc += xr[i] * g[i * 32 + lane];
#pragma unroll
        for (int o = 16; o > 0; o >>= 1) acc += __shfl_xor_sync(0xffffffffu, acc, o);
        l[e] = acc;
    }

    if (lane == 0) {
#pragma unroll
        for (int e = 0; e < E; e++) logits_out[(size_t)t * E + e] = l[e];
        // top-2 (first occurrence wins ties, matching jax top_k)
        int e0 = 0; float b0 = l[0];
#pragma unroll
        for (int e = 1; e < E; e++) if (l[e] > b0) { b0 = l[e]; e0 = e; }
        int e1 = (e0 == 0) ? 1 : 0; float b1 = l[e1];
#pragma unroll
        for (int e = 0; e < E; e++)
            if (e != e0 && l[e] > b1) { b1 = l[e]; e1 = e; }
        // renormalized top-2 softmax == pairwise softmax of top-2 logits
        float p = expf(b1 - b0);
        float inv = 1.f / (1.f + p);
        g_top_e[2 * t]     = e0; g_top_w[2 * t]     = inv;
        g_top_e[2 * t + 1] = e1; g_top_w[2 * t + 1] = p * inv;
        atomicAdd(&g_cnt[e0], 1);
        atomicAdd(&g_cnt[e1], 1);
    }
}

// ---------------------------------------------------------------------------
// 2) tiny exclusive scan (E=8)
// ---------------------------------------------------------------------------
__global__ void scan_kernel() {
    int off = 0;
    for (int e = 0; e < E; e++) { g_off[e] = off; g_cur[e] = off; off += g_cnt[e]; }
}

// ---------------------------------------------------------------------------
// 3) slot assignment (contiguous per-expert segments)
// ---------------------------------------------------------------------------
__global__ void assign_kernel() {
    int t = blockIdx.x * blockDim.x + threadIdx.x;
    if (t >= T) return;
#pragma unroll
    for (int k = 0; k < 2; k++) {
        int e = g_top_e[2 * t + k];
        int slot = atomicAdd(&g_cur[e], 1);
        g_assign_tok[slot] = t;
        g_assign_w[slot]   = g_top_w[2 * t + k];
        g_tok2slot[2 * t + k] = slot;
    }
}

// ---------------------------------------------------------------------------
// 4) GEMM1: for each expert segment, act = silu(X@w1) * (X@w3) * route_w
//    Block tile 128(M) x 64(N), K-tile 32. Dual-B (w1,w3) shares the gathered
//    A tile. 8 warps = 4(M) x 2(N), warp tile 32x32 per matrix.
// ---------------------------------------------------------------------------
__global__ __launch_bounds__(256) void gemm1_kernel(
    const float* __restrict__ x,
    const float* __restrict__ w1,
    const float* __restrict__ w3) {
    const int e = blockIdx.z;
    const int cnt = g_cnt[e];
    const int mt = blockIdx.y;
    if (mt * 128 >= cnt) return;
    const int off = g_off[e];
    const int n0 = blockIdx.x * 64;

    __shared__ uint32_t As[128][36];   // +4 pad: conflict-free frag loads
    __shared__ uint32_t B1s[32][72];   // +8 pad
    __shared__ uint32_t B3s[32][72];
    __shared__ int   stok[128];
    __shared__ float swt[128];

    const int tid = threadIdx.x;
    if (tid < 128) {
        int r = mt * 128 + tid;
        if (r < cnt) { stok[tid] = g_assign_tok[off + r]; swt[tid] = g_assign_w[off + r]; }
        else         { stok[tid] = 0;                     swt[tid] = 0.f; }
    }
    __syncthreads();

    const int lane = tid & 31, warp = tid >> 5;
    const int wm = warp >> 1;   // 0..3
    const int wn = warp & 1;    // 0..1
    const int lr = lane >> 2;   // groupID
    const int lc = lane & 3;    // threadID_in_group

    float accG[2][4][4];
    float accU[2][4][4];
#pragma unroll
    for (int i = 0; i < 2; i++)
#pragma unroll
        for (int j = 0; j < 4; j++)
#pragma unroll
            for (int c = 0; c < 4; c++) { accG[i][j][c] = 0.f; accU[i][j][c] = 0.f; }

    const size_t wbase = (size_t)e * H * F + n0;

    for (int k0 = 0; k0 < H; k0 += 32) {
        // A: 128x32 fp32 gathered rows -> tf32 in smem
#pragma unroll
        for (int v = 0; v < 4; v++) {
            int idx = tid + v * 256;
            int row = idx >> 3;
            int c4 = (idx & 7) << 2;
            const float4 f = *(const float4*)(x + (size_t)stok[row] * H + k0 + c4);
            *(uint4*)&As[row][c4] =
                make_uint4(f2tf32(f.x), f2tf32(f.y), f2tf32(f.z), f2tf32(f.w));
        }
        // B1/B3: 32x64 tiles
#pragma unroll
        for (int v = 0; v < 2; v++) {
            int idx = tid + v * 256;
            int row = idx >> 4;           // 0..31
            int c4 = (idx & 15) << 2;     // 0..60
            size_t gidx = wbase + (size_t)(k0 + row) * F + c4;
            float4 f1 = *(const float4*)(w1 + gidx);
            *(uint4*)&B1s[row][c4] =
                make_uint4(f2tf32(f1.x), f2tf32(f1.y), f2tf32(f1.z), f2tf32(f1.w));
            float4 f3 = *(const float4*)(w3 + gidx);
            *(uint4*)&B3s[row][c4] =
                make_uint4(f2tf32(f3.x), f2tf32(f3.y), f2tf32(f3.z), f2tf32(f3.w));
        }
        __syncthreads();

#pragma unroll
        for (int kk = 0; kk < 4; kk++) {
            uint32_t a[2][4];
#pragma unroll
            for (int mi = 0; mi < 2; mi++) {
                int r0 = wm * 32 + mi * 16 + lr;
                int cA = kk * 8 + lc;
                a[mi][0] = As[r0][cA];
                a[mi][1] = As[r0 + 8][cA];
                a[mi][2] = As[r0][cA + 4];
                a[mi][3] = As[r0 + 8][cA + 4];
            }
#pragma unroll
            for (int ni = 0; ni < 4; ni++) {
                int col = wn * 32 + ni * 8 + lr;
                int rB = kk * 8 + lc;
                uint32_t b1[2] = { B1s[rB][col], B1s[rB + 4][col] };
                uint32_t b3[2] = { B3s[rB][col], B3s[rB + 4][col] };
#pragma unroll
                for (int mi = 0; mi < 2; mi++) {
                    mma_tf32(accG[mi][ni], a[mi], b1);
                    mma_tf32(accU[mi][ni], a[mi], b3);
                }
            }
        }
        __syncthreads();
    }

    // Epilogue: act = route_w * u * silu(g)
#pragma unroll
    for (int mi = 0; mi < 2; mi++) {
#pragma unroll
        for (int half = 0; half < 2; half++) {
            int row = wm * 32 + mi * 16 + lr + half * 8;
            int grow = mt * 128 + row;
            if (grow < cnt) {
                float w = swt[row];
                float* dst = g_act + (size_t)(off + grow) * F + n0;
#pragma unroll
                for (int ni = 0; ni < 4; ni++) {
                    int col = wn * 32 + ni * 8 + lc * 2;
                    float gg = accG[mi][ni][half * 2 + 0];
                    float uu = accU[mi][ni][half * 2 + 0];
                    float a0 = w * uu * (gg / (1.f + expf(-gg)));
                    gg = accG[mi][ni][half * 2 + 1];
                    uu = accU[mi][ni][half * 2 + 1];
                    float a1 = w * uu * (gg / (1.f + expf(-gg)));
                    *(float2*)(dst + col) = make_float2(a0, a1);
                }
            }
        }
    }
}

// ---------------------------------------------------------------------------
// 5) GEMM2: y = act @ w2[e]   (K = 2816, N = 1024), contiguous A rows
// ---------------------------------------------------------------------------
__global__ __launch_bounds__(256) void gemm2_kernel(const float* __restrict__ w2) {
    const int e = blockIdx.z;
    const int cnt = g_cnt[e];
    const int mt = blockIdx.y;
    if (mt * 128 >= cnt) return;
    const int off = g_off[e];
    const int n0 = blockIdx.x * 64;

    __shared__ uint32_t As[128][36];
    __shared__ uint32_t Bs[32][72];

    const int tid = threadIdx.x;
    const int lane = tid & 31, warp = tid >> 5;
    const int wm = warp >> 1, wn = warp & 1;
    const int lr = lane >> 2, lc = lane & 3;

    float acc[2][4][4];
#pragma unroll
    for (int i = 0; i < 2; i++)
#pragma unroll
        for (int j = 0; j < 4; j++)
#pragma unroll
            for (int c = 0; c < 4; c++) acc[i][j][c] = 0.f;

    const float* Abase = g_act + (size_t)(off + mt * 128) * F;
    const size_t w2base = (size_t)e * F * H + n0;

    for (int k0 = 0; k0 < F; k0 += 32) {
#pragma unroll
        for (int v = 0; v < 4; v++) {
            int idx = tid + v * 256;
            int row = idx >> 3;
            int c4 = (idx & 7) << 2;
            const float4 f = *(const float4*)(Abase + (size_t)row * F + k0 + c4);
            *(uint4*)&As[row][c4] =
                make_uint4(f2tf32(f.x), f2tf32(f.y), f2tf32(f.z), f2tf32(f.w));
        }
#pragma unroll
        for (int v = 0; v < 2; v++) {
            int idx = tid + v * 256;
            int row = idx >> 4;
            int c4 = (idx & 15) << 2;
            const float4 f = *(const float4*)(w2 + w2base + (size_t)(k0 + row) * H + c4);
            *(uint4*)&Bs[row][c4] =
                make_uint4(f2tf32(f.x), f2tf32(f.y), f2tf32(f.z), f2tf32(f.w));
        }
        __syncthreads();

#pragma unroll
        for (int kk = 0; kk < 4; kk++) {
            uint32_t a[2][4];
#pragma unroll
            for (int mi = 0; mi < 2; mi++) {
                int r0 = wm * 32 + mi * 16 + lr;
                int cA = kk * 8 + lc;
                a[mi][0] = As[r0][cA];
                a[mi][1] = As[r0 + 8][cA];
                a[mi][2] = As[r0][cA + 4];
                a[mi][3] = As[r0 + 8][cA + 4];
            }
#pragma unroll
            for (int ni = 0; ni < 4; ni++) {
                int col = wn * 32 + ni * 8 + lr;
                int rB = kk * 8 + lc;
                uint32_t b[2] = { Bs[rB][col], Bs[rB + 4][col] };
#pragma unroll
                for (int mi = 0; mi < 2; mi++) mma_tf32(acc[mi][ni], a[mi], b);
            }
        }
        __syncthreads();
    }

#pragma unroll
    for (int mi = 0; mi < 2; mi++) {
#pragma unroll
        for (int half = 0; half < 2; half++) {
            int row = wm * 32 + mi * 16 + lr + half * 8;
            int grow = mt * 128 + row;
            if (grow < cnt) {
                float* dst = g_y + (size_t)(off + grow) * H + n0;
#pragma unroll
                for (int ni = 0; ni < 4; ni++) {
                    int col = wn * 32 + ni * 8 + lc * 2;
                    *(float2*)(dst + col) =
                        make_float2(acc[mi][ni][half * 2 + 0], acc[mi][ni][half * 2 + 1]);
                }
            }
        }
    }
}

// ---------------------------------------------------------------------------
// 6) combine: out[t] = y[slot0(t)] + y[slot1(t)]
// ---------------------------------------------------------------------------
__global__ void combine_kernel(float* __restrict__ out) {
    int t = blockIdx.x;
    int s0 = g_tok2slot[2 * t];
    int s1 = g_tok2slot[2 * t + 1];
    const float4* y0 = (const float4*)(g_y + (size_t)s0 * H);
    const float4* y1 = (const float4*)(g_y + (size_t)s1 * H);
    float4 a = y0[threadIdx.x];
    float4 b = y1[threadIdx.x];
    ((float4*)(out + (size_t)t * H))[threadIdx.x] =
        make_float4(a.x + b.x, a.y + b.y, a.z + b.z, a.w + b.w);
}

// ---------------------------------------------------------------------------
extern "C" void kernel_launch(void* const* d_in, const int* in_sizes, int n_in,
                              void* d_out, int out_size) {
    const float* x  = (const float*)d_in[0];   // hidden_states [2,1024,1024]
    const float* gw = (const float*)d_in[1];   // gate_w [8,1024]
    const float* w1 = (const float*)d_in[2];   // [8,1024,2816]
    const float* w3 = (const float*)d_in[3];   // [8,1024,2816]
    const float* w2 = (const float*)d_in[4];   // [8,2816,1024]
    float* out = (float*)d_out;

    // router_logits live after final_hidden_states in the concatenated output
    float* logits;
    if (out_size >= T * H + T * E) {
        logits = out + (size_t)T * H;
    } else {
        cudaGetSymbolAddress((void**)&logits, g_logits_dummy);
    }

    zero_counts_kernel<<<1, 32>>>();
    router_kernel<<<T / 8, 256>>>(x, gw, logits);
    scan_kernel<<<1, 1>>>();
    assign_kernel<<<(T + 255) / 256, 256>>>();
    gemm1_kernel<<<dim3(F / 64, 16, E), 256>>>(x, w1, w3);
    gemm2_kernel<<<dim3(H / 64, 16, E), 256>>>(w2);
    combine_kernel<<<T, 256>>>(out);
}

// round 7
// speedup vs baseline: 1.3837x; 1.3837x over previous
#include <cuda_runtime.h>
#include <stdint.h>
#include <math.h>

// Mixtral sparse MoE, GB300 sm_103a. T=2048, H=1024, E=8, F=2816, top-2.
constexpr int T = 2048, H = 1024, E = 8, F = 2816;
constexpr int AMAX = 2 * T, APAD = AMAX + 256;

__device__ uint32_t g_xg[(size_t)APAD * H];    // gathered tokens, tf32 bits
__device__ uint32_t g_act[(size_t)APAD * F];   // SwiGLU activations, tf32 bits
__device__ float    g_y[(size_t)AMAX * H];     // per-slot down proj
__device__ int   g_cnt[E], g_off[E], g_cur[E];
__device__ int   g_top_e[T * 2];
__device__ float g_top_w[T * 2];
__device__ int   g_assign_tok[AMAX];
__device__ float g_assign_w[AMAX];
__device__ int   g_tok2slot[T * 2];
__device__ float g_logits_dummy[T * E];

// ---------------- helpers ----------------
__device__ __forceinline__ uint32_t f2tf32(float f) {
    uint32_t u; asm("cvt.rna.tf32.f32 %0, %1;" : "=r"(u) : "f"(f)); return u;
}
__device__ __forceinline__ uint32_t t32(uint32_t raw) {  // raw f32 bits -> tf32 rna
    uint32_t u; asm("cvt.rna.tf32.f32 %0, %1;" : "=r"(u) : "f"(__uint_as_float(raw))); return u;
}
__device__ __forceinline__ void mma_tf32(float* c, const uint32_t* a, const uint32_t* b) {
    asm volatile(
        "mma.sync.aligned.m16n8k8.row.col.f32.tf32.tf32.f32 "
        "{%0,%1,%2,%3}, {%4,%5,%6,%7}, {%8,%9}, {%0,%1,%2,%3};\n"
        : "+f"(c[0]), "+f"(c[1]), "+f"(c[2]), "+f"(c[3])
        : "r"(a[0]), "r"(a[1]), "r"(a[2]), "r"(a[3]), "r"(b[0]), "r"(b[1]));
}
__device__ __forceinline__ uint32_t smem_u32(const void* p) {
    uint32_t a;
    asm("{ .reg .u64 t; cvta.to.shared.u64 t, %1; cvt.u32.u64 %0, t; }" : "=r"(a) : "l"(p));
    return a;
}
__device__ __forceinline__ void cpa16(uint32_t dst, const void* src) {
    asm volatile("cp.async.cg.shared.global [%0], [%1], 16;" :: "r"(dst), "l"(src));
}
__device__ __forceinline__ void cp_commit() { asm volatile("cp.async.commit_group;"); }
template <int N> __device__ __forceinline__ void cp_wait() {
    asm volatile("cp.async.wait_group %0;" :: "n"(N));
}

// ---------------- small kernels ----------------
__global__ void zero_counts_kernel() { if (threadIdx.x < E) g_cnt[threadIdx.x] = 0; }

__global__ __launch_bounds__(256) void router_kernel(
    const float* __restrict__ x, const float* __restrict__ gw, float* __restrict__ logits_out) {
    __shared__ float sgw[E * H];
    int tid = threadIdx.x;
    for (int i = tid; i < E * H; i += 256) sgw[i] = gw[i];
    __syncthreads();
    int warp = tid >> 5, lane = tid & 31;
    int t = blockIdx.x * 8 + warp;
    float xr[32];
    const float* xp = x + (size_t)t * H;
#pragma unroll
    for (int i = 0; i < 32; i++) xr[i] = xp[i * 32 + lane];
    float l[E];
#pragma unroll
    for (int e = 0; e < E; e++) {
        float acc = 0.f;
        const float* g = sgw + e * H;
#pragma unroll
        for (int i = 0; i < 32; i++) acc += xr[i] * g[i * 32 + lane];
#pragma unroll
        for (int o = 16; o > 0; o >>= 1) acc += __shfl_xor_sync(0xffffffffu, acc, o);
        l[e] = acc;
    }
    if (lane == 0) {
#pragma unroll
        for (int e = 0; e < E; e++) logits_out[(size_t)t * E + e] = l[e];
        int e0 = 0; float b0 = l[0];
#pragma unroll
        for (int e = 1; e < E; e++) if (l[e] > b0) { b0 = l[e]; e0 = e; }
        int e1 = (e0 == 0) ? 1 : 0; float b1 = l[e1];
#pragma unroll
        for (int e = 0; e < E; e++) if (e != e0 && l[e] > b1) { b1 = l[e]; e1 = e; }
        float p = expf(b1 - b0), inv = 1.f / (1.f + p);
        g_top_e[2 * t] = e0;     g_top_w[2 * t] = inv;
        g_top_e[2 * t + 1] = e1; g_top_w[2 * t + 1] = p * inv;
        atomicAdd(&g_cnt[e0], 1);
        atomicAdd(&g_cnt[e1], 1);
    }
}

__global__ void scan_kernel() {
    int off = 0;
    for (int e = 0; e < E; e++) { g_off[e] = off; g_cur[e] = off; off += g_cnt[e]; }
}

__global__ void assign_kernel() {
    int t = blockIdx.x * blockDim.x + threadIdx.x;
    if (t >= T) return;
#pragma unroll
    for (int k = 0; k < 2; k++) {
        int e = g_top_e[2 * t + k];
        int slot = atomicAdd(&g_cur[e], 1);
        g_assign_tok[slot] = t;
        g_assign_w[slot] = g_top_w[2 * t + k];
        g_tok2slot[2 * t + k] = slot;
    }
}

// gather + tf32-round token rows once (removes per-N-tile gather+cvt from GEMM1)
__global__ void gather_kernel(const float* __restrict__ x) {
    int slot = blockIdx.x;
    int tok = g_assign_tok[slot];
    float4 f = ((const float4*)(x + (size_t)tok * H))[threadIdx.x];
    ((uint4*)(g_xg + (size_t)slot * H))[threadIdx.x] =
        make_uint4(f2tf32(f.x), f2tf32(f.y), f2tf32(f.z), f2tf32(f.w));
}

// ---------------- GEMM1: act = rw * silu(X@w1) * (X@w3); tile 128x64, K-stage 32
constexpr int STG = 3;
constexpr int A_W = 128 * 36;   // words per A stage (pad 36)
constexpr int B_W = 32 * 72;    // words per B stage (pad 72)
constexpr int G1_SMEM = STG * (A_W + 2 * B_W) * 4;

__global__ void __launch_bounds__(256, 1) gemm1_kernel(
    const float* __restrict__ w1, const float* __restrict__ w3) {
    const int e = blockIdx.z, mt = blockIdx.y;
    const int cnt = g_cnt[e];
    if (mt * 128 >= cnt) return;
    const int off = g_off[e];
    const int n0 = blockIdx.x * 64;

    extern __shared__ uint32_t sm[];
    const uint32_t sb = smem_u32(sm);
    __shared__ float swt[128];

    const int tid = threadIdx.x;
    if (tid < 128) {
        int r = mt * 128 + tid;
        swt[tid] = (r < cnt) ? g_assign_w[off + r] : 0.f;
    }

    const uint32_t* Asrc = g_xg + (size_t)(off + mt * 128) * H;
    const float* B1src = w1 + (size_t)e * H * F + n0;
    const float* B3src = w3 + (size_t)e * H * F + n0;

    auto stage = [&](int s, int k0) {
        const uint32_t ab = sb + (s * A_W) * 4;
        const uint32_t b1b = sb + (STG * A_W + s * B_W) * 4;
        const uint32_t b3b = sb + (STG * A_W + (STG + s) * B_W) * 4;
#pragma unroll
        for (int v = 0; v < 4; v++) {
            int idx = tid + v * 256;
            int row = idx >> 3, c4 = (idx & 7) << 2;
            cpa16(ab + (row * 36 + c4) * 4, Asrc + (size_t)row * H + k0 + c4);
        }
#pragma unroll
        for (int v = 0; v < 2; v++) {
            int idx = tid + v * 256;
            int row = idx >> 4, c4 = (idx & 15) << 2;
            size_t g = (size_t)(k0 + row) * F + c4;
            cpa16(b1b + (row * 72 + c4) * 4, B1src + g);
            cpa16(b3b + (row * 72 + c4) * 4, B3src + g);
        }
    };

    const int lane = tid & 31, warp = tid >> 5;
    const int wm = warp >> 1, wn = warp & 1, lr = lane >> 2, lc = lane & 3;

    float accG[2][4][4], accU[2][4][4];
#pragma unroll
    for (int i = 0; i < 2; i++)
#pragma unroll
        for (int j = 0; j < 4; j++)
#pragma unroll
            for (int c = 0; c < 4; c++) { accG[i][j][c] = 0.f; accU[i][j][c] = 0.f; }

    stage(0, 0);  cp_commit();
    stage(1, 32); cp_commit();

    const int NK = H / 32;  // 32
    for (int i = 0; i < NK; i++) {
        cp_wait<STG - 2>();
        __syncthreads();
        int kn = i + STG - 1;
        if (kn < NK) stage(kn % STG, kn * 32);
        cp_commit();

        int s = i % STG;
        const uint32_t* As = sm + s * A_W;
        const uint32_t* Bs1 = sm + STG * A_W + s * B_W;
        const uint32_t* Bs3 = sm + STG * A_W + (STG + s) * B_W;
#pragma unroll
        for (int kk = 0; kk < 4; kk++) {
            uint32_t a[2][4];
#pragma unroll
            for (int mi = 0; mi < 2; mi++) {
                int r0 = wm * 32 + mi * 16 + lr, cA = kk * 8 + lc;
                a[mi][0] = As[r0 * 36 + cA];
                a[mi][1] = As[(r0 + 8) * 36 + cA];
                a[mi][2] = As[r0 * 36 + cA + 4];
                a[mi][3] = As[(r0 + 8) * 36 + cA + 4];
            }
#pragma unroll
            for (int ni = 0; ni < 4; ni++) {
                int col = wn * 32 + ni * 8 + lr, rB = kk * 8 + lc;
                uint32_t b1[2] = { t32(Bs1[rB * 72 + col]), t32(Bs1[(rB + 4) * 72 + col]) };
                uint32_t b3[2] = { t32(Bs3[rB * 72 + col]), t32(Bs3[(rB + 4) * 72 + col]) };
#pragma unroll
                for (int mi = 0; mi < 2; mi++) {
                    mma_tf32(accG[mi][ni], a[mi], b1);
                    mma_tf32(accU[mi][ni], a[mi], b3);
                }
            }
        }
    }

    // epilogue: act = rw * u * silu(g), stored as tf32 bits (GEMM2 reads raw)
#pragma unroll
    for (int mi = 0; mi < 2; mi++)
#pragma unroll
        for (int hf = 0; hf < 2; hf++) {
            int row = wm * 32 + mi * 16 + lr + hf * 8;
            int grow = mt * 128 + row;
            if (grow < cnt) {
                float w = swt[row];
                uint32_t* dst = g_act + (size_t)(off + grow) * F + n0;
#pragma unroll
                for (int ni = 0; ni < 4; ni++) {
                    int col = wn * 32 + ni * 8 + lc * 2;
                    float gg = accG[mi][ni][hf * 2], uu = accU[mi][ni][hf * 2];
                    float a0 = w * uu * (gg / (1.f + expf(-gg)));
                    gg = accG[mi][ni][hf * 2 + 1]; uu = accU[mi][ni][hf * 2 + 1];
                    float a1 = w * uu * (gg / (1.f + expf(-gg)));
                    *(uint2*)(dst + col) = make_uint2(f2tf32(a0), f2tf32(a1));
                }
            }
        }
}

// ---------------- GEMM2: y = act @ w2[e]; tile 128x128, K-stage 32 (K=2816)
constexpr int B2_W = 32 * 136;  // words per B stage (pad 136)
constexpr int G2_SMEM = STG * (A_W + B2_W) * 4;

__global__ void __launch_bounds__(256, 1) gemm2_kernel(const float* __restrict__ w2) {
    const int e = blockIdx.z, mt = blockIdx.y;
    const int cnt = g_cnt[e];
    if (mt * 128 >= cnt) return;
    const int off = g_off[e];
    const int n0 = blockIdx.x * 128;

    extern __shared__ uint32_t sm[];
    const uint32_t sb = smem_u32(sm);
    const int tid = threadIdx.x;

    const uint32_t* Asrc = g_act + (size_t)(off + mt * 128) * F;
    const float* Bsrc = w2 + (size_t)e * F * H + n0;

    auto stage = [&](int s, int k0) {
        const uint32_t ab = sb + (s * A_W) * 4;
        const uint32_t bb = sb + (STG * A_W + s * B2_W) * 4;
#pragma unroll
        for (int v = 0; v < 4; v++) {
            int idx = tid + v * 256;
            int row = idx >> 3, c4 = (idx & 7) << 2;
            cpa16(ab + (row * 36 + c4) * 4, Asrc + (size_t)row * F + k0 + c4);
        }
#pragma unroll
        for (int v = 0; v < 4; v++) {
            int idx = tid + v * 256;
            int row = idx >> 5, c4 = (idx & 31) << 2;
            cpa16(bb + (row * 136 + c4) * 4, Bsrc + (size_t)(k0 + row) * H + c4);
        }
    };

    const int lane = tid & 31, warp = tid >> 5;
    const int wm = warp >> 1, wn = warp & 1, lr = lane >> 2, lc = lane & 3;

    float acc[2][8][4];
#pragma unroll
    for (int i = 0; i < 2; i++)
#pragma unroll
        for (int j = 0; j < 8; j++)
#pragma unroll
            for (int c = 0; c < 4; c++) acc[i][j][c] = 0.f;

    stage(0, 0);  cp_commit();
    stage(1, 32); cp_commit();

    const int NK = F / 32;  // 88
    for (int i = 0; i < NK; i++) {
        cp_wait<STG - 2>();
        __syncthreads();
        int kn = i + STG - 1;
        if (kn < NK) stage(kn % STG, kn * 32);
        cp_commit();

        int s = i % STG;
        const uint32_t* As = sm + s * A_W;
        const uint32_t* Bs = sm + STG * A_W + s * B2_W;
#pragma unroll
        for (int kk = 0; kk < 4; kk++) {
            uint32_t a[2][4];
#pragma unroll
            for (int mi = 0; mi < 2; mi++) {
                int r0 = wm * 32 + mi * 16 + lr, cA = kk * 8 + lc;
                a[mi][0] = As[r0 * 36 + cA];
                a[mi][1] = As[(r0 + 8) * 36 + cA];
                a[mi][2] = As[r0 * 36 + cA + 4];
                a[mi][3] = As[(r0 + 8) * 36 + cA + 4];
            }
#pragma unroll
            for (int ni = 0; ni < 8; ni++) {
                int col = wn * 64 + ni * 8 + lr, rB = kk * 8 + lc;
                uint32_t b[2] = { t32(Bs[rB * 136 + col]), t32(Bs[(rB + 4) * 136 + col]) };
#pragma unroll
                for (int mi = 0; mi < 2; mi++) mma_tf32(acc[mi][ni], a[mi], b);
            }
        }
    }

#pragma unroll
    for (int mi = 0; mi < 2; mi++)
#pragma unroll
        for (int hf = 0; hf < 2; hf++) {
            int row = wm * 32 + mi * 16 + lr + hf * 8;
            int grow = mt * 128 + row;
            if (grow < cnt) {
                float* dst = g_y + (size_t)(off + grow) * H + n0;
#pragma unroll
                for (int ni = 0; ni < 8; ni++) {
                    int col = wn * 64 + ni * 8 + lc * 2;
                    *(float2*)(dst + col) =
                        make_float2(acc[mi][ni][hf * 2], acc[mi][ni][hf * 2 + 1]);
                }
            }
        }
}

// ---------------- combine ----------------
__global__ void combine_kernel(float* __restrict__ out) {
    int t = blockIdx.x;
    int s0 = g_tok2slot[2 * t], s1 = g_tok2slot[2 * t + 1];
    float4 a = ((const float4*)(g_y + (size_t)s0 * H))[threadIdx.x];
    float4 b = ((const float4*)(g_y + (size_t)s1 * H))[threadIdx.x];
    ((float4*)(out + (size_t)t * H))[threadIdx.x] =
        make_float4(a.x + b.x, a.y + b.y, a.z + b.z, a.w + b.w);
}

// ---------------- launch ----------------
extern "C" void kernel_launch(void* const* d_in, const int* in_sizes, int n_in,
                              void* d_out, int out_size) {
    const float* x  = (const float*)d_in[0];
    const float* gw = (const float*)d_in[1];
    const float* w1 = (const float*)d_in[2];
    const float* w3 = (const float*)d_in[3];
    const float* w2 = (const float*)d_in[4];
    float* out = (float*)d_out;

    float* logits;
    if (out_size >= T * H + T * E) logits = out + (size_t)T * H;
    else cudaGetSymbolAddress((void**)&logits, g_logits_dummy);

    cudaFuncSetAttribute(gemm1_kernel, cudaFuncAttributeMaxDynamicSharedMemorySize, G1_SMEM);
    cudaFuncSetAttribute(gemm2_kernel, cudaFuncAttributeMaxDynamicSharedMemorySize, G2_SMEM);

    zero_counts_kernel<<<1, 32>>>();
    router_kernel<<<T / 8, 256>>>(x, gw, logits);
    scan_kernel<<<1, 1>>>();
    assign_kernel<<<(T + 255) / 256, 256>>>();
    gather_kernel<<<AMAX, 256>>>(x);
    gemm1_kernel<<<dim3(F / 64, 16, E), 256, G1_SMEM>>>(w1, w3);
    gemm2_kernel<<<dim3(H / 128, 16, E), 256, G2_SMEM>>>(w2);
    combine_kernel<<<T, 256>>>(out);
}